// round 1
// baseline (speedup 1.0000x reference)
#include <cuda_runtime.h>
#include <cuda_bf16.h>
#include <cstdint>

// Problem constants (shapes fixed by the dataset)
#define MAX_N 100000
#define DIM   160
#define NS    64
#define NV    32

// ---- device scratch (no allocs allowed) ----
__device__ __align__(16) float g_msg[MAX_N * DIM];    // 64 MB segment-sum buffer
__device__ float g_Wcs[192 * 96];                     // combined s-path weights
__device__ float g_Wc1[128 * 32];                     // combined v-path (outer-product part)
__device__ float g_Wc2[64 * 32];                      // combined v-path (per-channel part)

// ---------------------------------------------------------------------------
// Kernel 1: fold all scale factors / tp-weight vectors into combined matrices
// ---------------------------------------------------------------------------
__global__ void prep_weights(const float* __restrict__ Wls,   // [96][96]
                             const float* __restrict__ Wlv,   // [96][32]
                             const float* __restrict__ W000,  // [64][96]
                             const float* __restrict__ W110,  // [32][96]
                             const float* __restrict__ W011,  // [64][32]
                             const float* __restrict__ W101,  // [32][32]
                             const float* __restrict__ w00,   // [64]
                             const float* __restrict__ w01,   // [64]
                             const float* __restrict__ w10,   // [32]
                             const float* __restrict__ w11)   // [32]
{
    int i = blockIdx.x * blockDim.x + threadIdx.x;
    const float inv_fan = rsqrtf(96.f);
    const float inv2    = rsqrtf(2.f);
    const float s64     = inv2 * rsqrtf(64.f);
    const float s32     = inv2 * rsqrtf(32.f);

    if (i < 192 * 96) {
        int u = i / 96, w = i - u * 96;
        float v;
        if      (u < 64)  v = Wls[u * 96 + w] * inv_fan * w00[u];
        else if (u < 96)  v = Wls[u * 96 + w] * inv_fan * w11[u - 64];
        else if (u < 160) v = W000[(u - 96) * 96 + w] * s64;
        else              v = W110[(u - 160) * 96 + w] * s32;
        g_Wcs[i] = v;
    } else if (i < 192 * 96 + 128 * 32) {
        int j = i - 192 * 96;
        int u = j / 32, w = j - u * 32;
        float v;
        if (u < 64) v = Wlv[u * 32 + w] * inv_fan * w01[u];
        else        v = W011[(u - 64) * 32 + w] * s64;
        g_Wc1[j] = v;
    } else if (i < 192 * 96 + 128 * 32 + 64 * 32) {
        int j = i - (192 * 96 + 128 * 32);
        int u = j / 32, w = j - u * 32;
        float v;
        if (u < 32) v = Wlv[(64 + u) * 32 + w] * inv_fan * w10[u];
        else        v = W101[(u - 32) * 32 + w] * s32;
        g_Wc2[j] = v;
    }
}

// ---------------------------------------------------------------------------
// Kernel 2: zero the segment-sum buffer
// ---------------------------------------------------------------------------
__global__ void zero_msg(int n4)
{
    int i = blockIdx.x * blockDim.x + threadIdx.x;
    if (i < n4) reinterpret_cast<float4*>(g_msg)[i] = make_float4(0.f, 0.f, 0.f, 0.f);
}

// ---------------------------------------------------------------------------
// Kernel 3: scatter-add edge messages with vectorized global reductions
// One thread per (edge, float4-chunk): 40 chunks of 16B per 160-float row.
// ---------------------------------------------------------------------------
__global__ void scatter_edges(const float4* __restrict__ em,
                              const int*    __restrict__ eidx,
                              int E)
{
    int i = blockIdx.x * blockDim.x + threadIdx.x;
    if (i >= E * 40) return;
    int e = i / 40;
    int j = i - e * 40;
    float4 v = em[i];                      // coalesced: row-major [E][40] float4
    int dst  = __ldg(eidx + E + e);        // edge_index row 1 = destination
    float* p = g_msg + (size_t)dst * DIM + j * 4;   // 16B-aligned (640B rows)
    asm volatile("red.global.add.v4.f32 [%0], {%1, %2, %3, %4};"
                 :: "l"(p), "f"(v.x), "f"(v.y), "f"(v.z), "f"(v.w)
                 : "memory");
}

// ---------------------------------------------------------------------------
// Kernel 4: fused per-node update.
// Block = 256 threads = 8 warps, 64 nodes per block (8 nodes per warp, M=8
// register blocking). Per-node U vectors (512 floats) staged in shared:
//   [  0:192) U_s  = [a_s*ms | (mv.a_v)/sqrt3 | a_s*xs | (xv.a_v)/sqrt3]
//   [192:320) U_1  = [ms | xs]
//   [320:512) U_2  = for c in 0..2: [a_s*mv[:,c] (32) | a_s*xv[:,c] (32)]
// Weights streamed from global (L1-resident, ~97 KB total).
// ---------------------------------------------------------------------------
__global__ void __launch_bounds__(256, 1)
node_update(const float* __restrict__ feats,
            const float* __restrict__ attrs,
            float*       __restrict__ out,
            int N)
{
    extern __shared__ float sm[];
    float* sU  = sm;             // 64 * 512
    float* sAv = sm + 64 * 512;  // 64 * 3

    const float rs5  = 0.44721359549995794f;  // 1/sqrt(5)
    const float inv3 = 0.5773502691896258f;   // 1/sqrt(3)

    const int t    = threadIdx.x;
    const int base = blockIdx.x * 64;

    // ---- prologue: build U vectors (4 threads per node) ----
    {
        int i  = t >> 2;
        int t4 = t & 3;
        int n  = base + i;
        float* u = sU + i * 512;
        if (n < N) {
            float a0  = __ldg(attrs + n * 4 + 0);
            float av0 = __ldg(attrs + n * 4 + 1);
            float av1 = __ldg(attrs + n * 4 + 2);
            float av2 = __ldg(attrs + n * 4 + 3);
            if (t4 == 0) {
                sAv[i * 3 + 0] = av0; sAv[i * 3 + 1] = av1; sAv[i * 3 + 2] = av2;
            }
            const float* mrow = g_msg + (size_t)n * DIM;
            const float* frow = feats + (size_t)n * DIM;
            #pragma unroll 4
            for (int k = t4; k < 64; k += 4) {
                float ms = mrow[k] * rs5;
                float xs = __ldg(frow + k);
                u[k]       = a0 * ms;   // U_s block 0
                u[96 + k]  = a0 * xs;   // U_s block 2
                u[192 + k] = ms;        // U_1 block 0
                u[256 + k] = xs;        // U_1 block 1
            }
            #pragma unroll 2
            for (int k = t4; k < 32; k += 4) {
                float m0 = mrow[64 + k * 3 + 0] * rs5;
                float m1 = mrow[64 + k * 3 + 1] * rs5;
                float m2 = mrow[64 + k * 3 + 2] * rs5;
                float x0 = __ldg(frow + 64 + k * 3 + 0);
                float x1 = __ldg(frow + 64 + k * 3 + 1);
                float x2 = __ldg(frow + 64 + k * 3 + 2);
                u[64 + k]  = (m0 * av0 + m1 * av1 + m2 * av2) * inv3;  // dmv
                u[160 + k] = (x0 * av0 + x1 * av1 + x2 * av2) * inv3;  // dxv
                // U_2: c-major blocks of 64 = [a_s*mv[:,c] | a_s*xv[:,c]]
                u[320 + k]        = a0 * m0;
                u[320 + 64 + k]   = a0 * m1;
                u[320 + 128 + k]  = a0 * m2;
                u[352 + k]        = a0 * x0;
                u[352 + 64 + k]   = a0 * x1;
                u[352 + 128 + k]  = a0 * x2;
            }
        } else {
            #pragma unroll 8
            for (int k = t4; k < 512; k += 4) u[k] = 0.f;
            if (t4 == 0) { sAv[i*3] = 0.f; sAv[i*3+1] = 0.f; sAv[i*3+2] = 0.f; }
        }
    }
    __syncthreads();

    const int lane = t & 31;
    const int i0   = (t >> 5) * 8;          // first node slot for this warp
    const int nvalid = N - base;            // valid slots in this block (<=64)

    // ---- s-path GEMM: h_s[96] = U_s[192] . Wc_s[192][96] ----
    float a0[8], a1[8], a2[8];
    #pragma unroll
    for (int m = 0; m < 8; m++) { a0[m] = 0.f; a1[m] = 0.f; a2[m] = 0.f; }

    #pragma unroll 4
    for (int u = 0; u < 192; ++u) {
        float w0 = __ldg(g_Wcs + u * 96 + lane);
        float w1 = __ldg(g_Wcs + u * 96 + 32 + lane);
        float w2 = __ldg(g_Wcs + u * 96 + 64 + lane);
        #pragma unroll
        for (int m = 0; m < 8; m++) {
            float b = sU[(i0 + m) * 512 + u];
            a0[m] = fmaf(b, w0, a0[m]);
            a1[m] = fmaf(b, w1, a1[m]);
            a2[m] = fmaf(b, w2, a2[m]);
        }
    }

    // s epilogue: silu on first 64 outputs, sigmoid gates on last 32 (kept in regs)
    float g[8];
    #pragma unroll
    for (int m = 0; m < 8; m++) {
        g[m] = 1.f / (1.f + __expf(-a2[m]));
        if (i0 + m < nvalid) {
            float* orow = out + (size_t)(base + i0 + m) * DIM;
            orow[lane]      = a0[m] / (1.f + __expf(-a0[m]));
            orow[lane + 32] = a1[m] / (1.f + __expf(-a1[m]));
        }
    }

    // ---- v-path GEMM 1: G1[32] = U_1[128] . Wc_1[128][32] ----
    float v1[8];
    #pragma unroll
    for (int m = 0; m < 8; m++) v1[m] = 0.f;
    #pragma unroll 4
    for (int u = 0; u < 128; ++u) {
        float wv = __ldg(g_Wc1 + u * 32 + lane);
        #pragma unroll
        for (int m = 0; m < 8; m++)
            v1[m] = fmaf(sU[(i0 + m) * 512 + 192 + u], wv, v1[m]);
    }

    // ---- v-path GEMM 2: G2[32][c] = U_2c[64] . Wc_2[64][32] ----
    float p0[8], p1[8], p2[8];
    #pragma unroll
    for (int m = 0; m < 8; m++) { p0[m] = 0.f; p1[m] = 0.f; p2[m] = 0.f; }
    #pragma unroll 4
    for (int u = 0; u < 64; ++u) {
        float wv = __ldg(g_Wc2 + u * 32 + lane);
        #pragma unroll
        for (int m = 0; m < 8; m++) {
            const float* b = sU + (i0 + m) * 512 + 320;
            p0[m] = fmaf(b[u],       wv, p0[m]);
            p1[m] = fmaf(b[64 + u],  wv, p1[m]);
            p2[m] = fmaf(b[128 + u], wv, p2[m]);
        }
    }

    // v epilogue: h_v = G1*a_v_c + G2c ; out_v = gate * h_v
    #pragma unroll
    for (int m = 0; m < 8; m++) {
        if (i0 + m < nvalid) {
            float av0 = sAv[(i0 + m) * 3 + 0];
            float av1 = sAv[(i0 + m) * 3 + 1];
            float av2 = sAv[(i0 + m) * 3 + 2];
            float* orow = out + (size_t)(base + i0 + m) * DIM + NS + lane * 3;
            orow[0] = g[m] * fmaf(v1[m], av0, p0[m]);
            orow[1] = g[m] * fmaf(v1[m], av1, p1[m]);
            orow[2] = g[m] * fmaf(v1[m], av2, p2[m]);
        }
    }
}

// ---------------------------------------------------------------------------
extern "C" void kernel_launch(void* const* d_in, const int* in_sizes, int n_in,
                              void* d_out, int out_size)
{
    const float* feats = (const float*)d_in[0];   // node_feats [N,160]
    const float* attrs = (const float*)d_in[1];   // node_attrs [N,4]
    const float* emsg  = (const float*)d_in[2];   // edge_message [E,160]
    const int*   eidx  = (const int*)  d_in[3];   // edge_index [2,E]
    const float* w00   = (const float*)d_in[4];
    const float* w01   = (const float*)d_in[5];
    const float* w10   = (const float*)d_in[6];
    const float* w11   = (const float*)d_in[7];
    const float* Wls   = (const float*)d_in[8];
    const float* Wlv   = (const float*)d_in[9];
    const float* W000  = (const float*)d_in[10];
    const float* W110  = (const float*)d_in[11];
    const float* W011  = (const float*)d_in[12];
    const float* W101  = (const float*)d_in[13];

    int N = in_sizes[0] / DIM;
    int E = in_sizes[2] / DIM;

    const int smem_bytes = 64 * 512 * 4 + 64 * 3 * 4;  // 131840
    cudaFuncSetAttribute(node_update,
                         cudaFuncAttributeMaxDynamicSharedMemorySize, smem_bytes);

    // 1. fold weights
    prep_weights<<<(192 * 96 + 128 * 32 + 64 * 32 + 255) / 256, 256>>>(
        Wls, Wlv, W000, W110, W011, W101, w00, w01, w10, w11);

    // 2. zero the segment-sum buffer
    int n4 = N * (DIM / 4);
    zero_msg<<<(n4 + 255) / 256, 256>>>(n4);

    // 3. scatter-add edge messages
    long total = (long)E * 40;
    scatter_edges<<<(int)((total + 255) / 256), 256>>>(
        (const float4*)emsg, eidx, E);

    // 4. fused node update
    int blocks = (N + 63) / 64;
    node_update<<<blocks, 256, smem_bytes>>>(feats, attrs, (float*)d_out, N);
}

// round 2
// speedup vs baseline: 1.4463x; 1.4463x over previous
#include <cuda_runtime.h>
#include <cuda_bf16.h>
#include <cstdint>

// Problem constants (shapes fixed by the dataset)
#define MAX_N 100000
#define DIM   160
#define NS    64
#define NV    32

typedef unsigned long long ull;

// ---- device scratch (no allocs allowed) ----
__device__ __align__(16) float g_msg[MAX_N * DIM];  // 64 MB segment-sum buffer
// Weight matrices pre-paired along K: element [u2][o] = {W[2*u2][o], W[2*u2+1][o]}
__device__ ull g_Wcs2[96 * 96];   // s-path   (K=192 -> 96 pairs, 96 outputs)
__device__ ull g_Wc1p[64 * 32];   // v-path 1 (K=128 -> 64 pairs, 32 outputs)
__device__ ull g_Wc2p[32 * 32];   // v-path 2 (K=64  -> 32 pairs, 32 outputs)

__device__ __forceinline__ ull pack2(float lo, float hi) {
    return (ull)__float_as_uint(lo) | ((ull)__float_as_uint(hi) << 32);
}
__device__ __forceinline__ float hsum2(ull v) {
    return __uint_as_float((unsigned)v) + __uint_as_float((unsigned)(v >> 32));
}
#define FMA2(acc, a, b) \
    asm("fma.rn.f32x2 %0, %1, %2, %3;" : "=l"(acc) : "l"(a), "l"(b), "l"(acc))

// ---------------------------------------------------------------------------
// Kernel 1: fold scale factors / tp-weight vectors into combined, K-paired mats
// ---------------------------------------------------------------------------
__device__ __forceinline__ float comb_s(int u, int o,
                                        const float* Wls, const float* W000,
                                        const float* W110, const float* w00,
                                        const float* w11) {
    const float inv_fan = rsqrtf(96.f);
    const float inv2 = rsqrtf(2.f);
    if (u < 64)  return Wls[u * 96 + o] * inv_fan * w00[u];
    if (u < 96)  return Wls[u * 96 + o] * inv_fan * w11[u - 64];
    if (u < 160) return W000[(u - 96) * 96 + o] * inv2 * rsqrtf(64.f);
    return W110[(u - 160) * 96 + o] * inv2 * rsqrtf(32.f);
}
__device__ __forceinline__ float comb_1(int u, int o,
                                        const float* Wlv, const float* W011,
                                        const float* w01) {
    const float inv_fan = rsqrtf(96.f);
    const float inv2 = rsqrtf(2.f);
    if (u < 64) return Wlv[u * 32 + o] * inv_fan * w01[u];
    return W011[(u - 64) * 32 + o] * inv2 * rsqrtf(64.f);
}
__device__ __forceinline__ float comb_2(int u, int o,
                                        const float* Wlv, const float* W101,
                                        const float* w10) {
    const float inv_fan = rsqrtf(96.f);
    const float inv2 = rsqrtf(2.f);
    if (u < 32) return Wlv[(64 + u) * 32 + o] * inv_fan * w10[u];
    return W101[(u - 32) * 32 + o] * inv2 * rsqrtf(32.f);
}

__global__ void prep_weights(const float* __restrict__ Wls,
                             const float* __restrict__ Wlv,
                             const float* __restrict__ W000,
                             const float* __restrict__ W110,
                             const float* __restrict__ W011,
                             const float* __restrict__ W101,
                             const float* __restrict__ w00,
                             const float* __restrict__ w01,
                             const float* __restrict__ w10,
                             const float* __restrict__ w11)
{
    int i = blockIdx.x * blockDim.x + threadIdx.x;
    if (i < 96 * 96) {
        int u2 = i / 96, o = i - u2 * 96;
        g_Wcs2[i] = pack2(comb_s(2 * u2, o, Wls, W000, W110, w00, w11),
                          comb_s(2 * u2 + 1, o, Wls, W000, W110, w00, w11));
    } else if (i < 96 * 96 + 64 * 32) {
        int j = i - 96 * 96;
        int u2 = j / 32, o = j - u2 * 32;
        g_Wc1p[j] = pack2(comb_1(2 * u2, o, Wlv, W011, w01),
                          comb_1(2 * u2 + 1, o, Wlv, W011, w01));
    } else if (i < 96 * 96 + 64 * 32 + 32 * 32) {
        int j = i - (96 * 96 + 64 * 32);
        int u2 = j / 32, o = j - u2 * 32;
        g_Wc2p[j] = pack2(comb_2(2 * u2, o, Wlv, W101, w10),
                          comb_2(2 * u2 + 1, o, Wlv, W101, w10));
    }
}

// ---------------------------------------------------------------------------
// Kernel 2: zero the segment-sum buffer
// ---------------------------------------------------------------------------
__global__ void zero_msg(int n4)
{
    int i = blockIdx.x * blockDim.x + threadIdx.x;
    if (i < n4) reinterpret_cast<float4*>(g_msg)[i] = make_float4(0.f, 0.f, 0.f, 0.f);
}

// ---------------------------------------------------------------------------
// Kernel 3: scatter-add edge messages with vectorized global reductions
// ---------------------------------------------------------------------------
__global__ void scatter_edges(const float4* __restrict__ em,
                              const int*    __restrict__ eidx,
                              int E)
{
    int i = blockIdx.x * blockDim.x + threadIdx.x;
    if (i >= E * 40) return;
    int e = i / 40;
    int j = i - e * 40;
    float4 v = em[i];
    int dst  = __ldg(eidx + E + e);
    float* p = g_msg + (size_t)dst * DIM + j * 4;
    asm volatile("red.global.add.v4.f32 [%0], {%1, %2, %3, %4};"
                 :: "l"(p), "f"(v.x), "f"(v.y), "f"(v.z), "f"(v.w)
                 : "memory");
}

// ---------------------------------------------------------------------------
// Kernel 4: fused per-node update. 512 threads = 16 warps, 64 nodes/block,
// M=4 nodes per warp. Inner products use fma.rn.f32x2 with K paired in twos:
// b-pair = one LDS.64 from the U staging buffer, w-pair = one LDG.64 from the
// pre-paired weight arrays. Per-node U layout (512 floats):
//   [  0:192) U_s  = [a_s*ms | (mv.a_v)/sqrt3 | a_s*xs | (xv.a_v)/sqrt3]
//   [192:320) U_1  = [ms | xs]
//   [320:512) U_2  = for c in 0..2: [a_s*mv[:,c] (32) | a_s*xv[:,c] (32)]
// ---------------------------------------------------------------------------
__global__ void __launch_bounds__(512, 1)
node_update(const float* __restrict__ feats,
            const float* __restrict__ attrs,
            float*       __restrict__ out,
            int N)
{
    extern __shared__ float sm[];
    float* sU  = sm;             // 64 * 512
    float* sAv = sm + 64 * 512;  // 64 * 3

    const float rs5  = 0.44721359549995794f;  // 1/sqrt(5)
    const float inv3 = 0.5773502691896258f;   // 1/sqrt(3)

    const int t    = threadIdx.x;
    const int base = blockIdx.x * 64;

    // ---- prologue: build U vectors (8 threads per node) ----
    {
        int i  = t >> 3;
        int t8 = t & 7;
        int n  = base + i;
        float* u = sU + i * 512;
        if (n < N) {
            float a0  = __ldg(attrs + n * 4 + 0);
            float av0 = __ldg(attrs + n * 4 + 1);
            float av1 = __ldg(attrs + n * 4 + 2);
            float av2 = __ldg(attrs + n * 4 + 3);
            if (t8 == 0) {
                sAv[i * 3 + 0] = av0; sAv[i * 3 + 1] = av1; sAv[i * 3 + 2] = av2;
            }
            const float* mrow = g_msg + (size_t)n * DIM;
            const float* frow = feats + (size_t)n * DIM;
            #pragma unroll
            for (int k = t8; k < 64; k += 8) {
                float ms = mrow[k] * rs5;
                float xs = __ldg(frow + k);
                u[k]       = a0 * ms;
                u[96 + k]  = a0 * xs;
                u[192 + k] = ms;
                u[256 + k] = xs;
            }
            #pragma unroll
            for (int k = t8; k < 32; k += 8) {
                float m0 = mrow[64 + k * 3 + 0] * rs5;
                float m1 = mrow[64 + k * 3 + 1] * rs5;
                float m2 = mrow[64 + k * 3 + 2] * rs5;
                float x0 = __ldg(frow + 64 + k * 3 + 0);
                float x1 = __ldg(frow + 64 + k * 3 + 1);
                float x2 = __ldg(frow + 64 + k * 3 + 2);
                u[64 + k]  = (m0 * av0 + m1 * av1 + m2 * av2) * inv3;
                u[160 + k] = (x0 * av0 + x1 * av1 + x2 * av2) * inv3;
                u[320 + k]       = a0 * m0;
                u[320 + 64 + k]  = a0 * m1;
                u[320 + 128 + k] = a0 * m2;
                u[352 + k]       = a0 * x0;
                u[352 + 64 + k]  = a0 * x1;
                u[352 + 128 + k] = a0 * x2;
            }
        } else {
            #pragma unroll
            for (int k = t8; k < 512; k += 8) u[k] = 0.f;
            if (t8 == 0) { sAv[i*3] = 0.f; sAv[i*3+1] = 0.f; sAv[i*3+2] = 0.f; }
        }
    }
    __syncthreads();

    const int lane   = t & 31;
    const int i0     = (t >> 5) * 4;      // first node slot for this warp (M=4)
    const int nvalid = N - base;

    // ---- s-path GEMM: h_s[96] = U_s[192] . Wc_s[192][96], K-paired ----
    ull a0[4], a1[4], a2[4];
    #pragma unroll
    for (int m = 0; m < 4; m++) { a0[m] = 0ull; a1[m] = 0ull; a2[m] = 0ull; }

    #pragma unroll 4
    for (int u2 = 0; u2 < 96; ++u2) {
        ull w0 = __ldg(g_Wcs2 + u2 * 96 + lane);
        ull w1 = __ldg(g_Wcs2 + u2 * 96 + 32 + lane);
        ull w2 = __ldg(g_Wcs2 + u2 * 96 + 64 + lane);
        #pragma unroll
        for (int m = 0; m < 4; m++) {
            ull b = *(const ull*)(sU + (i0 + m) * 512 + u2 * 2);
            FMA2(a0[m], b, w0);
            FMA2(a1[m], b, w1);
            FMA2(a2[m], b, w2);
        }
    }

    // s epilogue: silu on first 64 outputs, sigmoid gates kept in regs
    float g[4];
    #pragma unroll
    for (int m = 0; m < 4; m++) {
        float h0 = hsum2(a0[m]);
        float h1 = hsum2(a1[m]);
        float h2 = hsum2(a2[m]);
        g[m] = 1.f / (1.f + __expf(-h2));
        if (i0 + m < nvalid) {
            float* orow = out + (size_t)(base + i0 + m) * DIM;
            orow[lane]      = h0 / (1.f + __expf(-h0));
            orow[lane + 32] = h1 / (1.f + __expf(-h1));
        }
    }

    // ---- v-path GEMM 1: G1[32] = U_1[128] . Wc_1[128][32], K-paired ----
    ull v1[4];
    #pragma unroll
    for (int m = 0; m < 4; m++) v1[m] = 0ull;
    #pragma unroll 4
    for (int u2 = 0; u2 < 64; ++u2) {
        ull wv = __ldg(g_Wc1p + u2 * 32 + lane);
        #pragma unroll
        for (int m = 0; m < 4; m++) {
            ull b = *(const ull*)(sU + (i0 + m) * 512 + 192 + u2 * 2);
            FMA2(v1[m], b, wv);
        }
    }

    // ---- v-path GEMM 2: G2[32][c] = U_2c[64] . Wc_2[64][32], K-paired ----
    ull p0[4], p1[4], p2[4];
    #pragma unroll
    for (int m = 0; m < 4; m++) { p0[m] = 0ull; p1[m] = 0ull; p2[m] = 0ull; }
    #pragma unroll 4
    for (int u2 = 0; u2 < 32; ++u2) {
        ull wv = __ldg(g_Wc2p + u2 * 32 + lane);
        #pragma unroll
        for (int m = 0; m < 4; m++) {
            const float* b = sU + (i0 + m) * 512 + 320;
            ull b0 = *(const ull*)(b + u2 * 2);
            ull b1 = *(const ull*)(b + 64 + u2 * 2);
            ull b2 = *(const ull*)(b + 128 + u2 * 2);
            FMA2(p0[m], b0, wv);
            FMA2(p1[m], b1, wv);
            FMA2(p2[m], b2, wv);
        }
    }

    // v epilogue: h_v = G1*a_v_c + G2c ; out_v = gate * h_v
    #pragma unroll
    for (int m = 0; m < 4; m++) {
        if (i0 + m < nvalid) {
            float av0 = sAv[(i0 + m) * 3 + 0];
            float av1 = sAv[(i0 + m) * 3 + 1];
            float av2 = sAv[(i0 + m) * 3 + 2];
            float vg  = hsum2(v1[m]);
            float* orow = out + (size_t)(base + i0 + m) * DIM + NS + lane * 3;
            orow[0] = g[m] * fmaf(vg, av0, hsum2(p0[m]));
            orow[1] = g[m] * fmaf(vg, av1, hsum2(p1[m]));
            orow[2] = g[m] * fmaf(vg, av2, hsum2(p2[m]));
        }
    }
}

// ---------------------------------------------------------------------------
extern "C" void kernel_launch(void* const* d_in, const int* in_sizes, int n_in,
                              void* d_out, int out_size)
{
    const float* feats = (const float*)d_in[0];
    const float* attrs = (const float*)d_in[1];
    const float* emsg  = (const float*)d_in[2];
    const int*   eidx  = (const int*)  d_in[3];
    const float* w00   = (const float*)d_in[4];
    const float* w01   = (const float*)d_in[5];
    const float* w10   = (const float*)d_in[6];
    const float* w11   = (const float*)d_in[7];
    const float* Wls   = (const float*)d_in[8];
    const float* Wlv   = (const float*)d_in[9];
    const float* W000  = (const float*)d_in[10];
    const float* W110  = (const float*)d_in[11];
    const float* W011  = (const float*)d_in[12];
    const float* W101  = (const float*)d_in[13];

    int N = in_sizes[0] / DIM;
    int E = in_sizes[2] / DIM;

    const int smem_bytes = 64 * 512 * 4 + 64 * 3 * 4;  // 131840
    cudaFuncSetAttribute(node_update,
                         cudaFuncAttributeMaxDynamicSharedMemorySize, smem_bytes);

    // 1. fold weights into paired layout
    int prep_elems = 96 * 96 + 64 * 32 + 32 * 32;
    prep_weights<<<(prep_elems + 255) / 256, 256>>>(
        Wls, Wlv, W000, W110, W011, W101, w00, w01, w10, w11);

    // 2. zero the segment-sum buffer
    int n4 = N * (DIM / 4);
    zero_msg<<<(n4 + 255) / 256, 256>>>(n4);

    // 3. scatter-add edge messages
    long total = (long)E * 40;
    scatter_edges<<<(int)((total + 255) / 256), 256>>>(
        (const float4*)emsg, eidx, E);

    // 4. fused node update
    int blocks = (N + 63) / 64;
    node_update<<<blocks, 512, smem_bytes>>>(feats, attrs, (float*)d_out, N);
}